// round 16
// baseline (speedup 1.0000x reference)
#include <cuda_runtime.h>
#include <cuda_fp16.h>
#include <cstdint>
#include <math.h>

// Problem constants
#define B_   512
#define L_   64
#define H_   16
#define DH_  64
#define D_   1024
#define M_   (B_ * L_)        // 32768
#define K1_  1024             // fp16 K
#define NT_  (K1_ / 64)       // 16 K-tiles of 64 halfs

// ---------------------------------------------------------------------------
// Scratch (__device__ globals — no allocations allowed)
// ---------------------------------------------------------------------------
__device__ __half g_xs  [(size_t)M_ * K1_];        // x fp16      [M, 1024]
__device__ __half g_ats [(size_t)M_ * K1_];        // attn fp16   [M, 1024]
__device__ __half g_wqkv[(size_t)3 * D_ * K1_];    // [Wq;Wk;Wv]^T fp16
__device__ __half g_wo  [(size_t)D_ * K1_];        // Wo^T fp16
__device__ float  g_qk  [(size_t)M_ * 2048];       // [M, 2048]: Q | K fp32
__device__ __half g_vh  [(size_t)M_ * 1024];       // [M, 1024]: V fp16

__device__ __forceinline__ __half2 split1(float v) {
    __half hi = __float2half_rn(v);
    __half lo = __float2half_rn(v - __half2float(hi));
    __half2 p; p.x = hi; p.y = lo; return p;
}

// ---------------------------------------------------------------------------
// fp32 -> fp16 conversions
// ---------------------------------------------------------------------------
__global__ __launch_bounds__(256) void conv_rows(
    const float* __restrict__ in, __half* __restrict__ out, int n8)
{
    int i = blockIdx.x * blockDim.x + threadIdx.x;
    if (i >= n8) return;
    float4 a = ((const float4*)in)[2 * i];
    float4 b = ((const float4*)in)[2 * i + 1];
    union { uint4 u; __half2 p[4]; } pk;
    pk.p[0] = __floats2half2_rn(a.x, a.y);
    pk.p[1] = __floats2half2_rn(a.z, a.w);
    pk.p[2] = __floats2half2_rn(b.x, b.y);
    pk.p[3] = __floats2half2_rn(b.z, b.w);
    ((uint4*)out)[i] = pk.u;
}

__global__ __launch_bounds__(256) void conv_w_t(
    const float* __restrict__ W0, const float* __restrict__ W1,
    const float* __restrict__ W2, const float* __restrict__ W3,
    __half* __restrict__ O0, __half* __restrict__ O3)
{
    __shared__ float t[32][33];
    const int which = blockIdx.z;
    const float* W = (which == 0) ? W0 : (which == 1) ? W1 : (which == 2) ? W2 : W3;
    __half* Wt = (which == 3) ? O3 : (O0 + (size_t)which * D_ * K1_);

    const int bn = blockIdx.x, bk = blockIdx.y;
    const int tx = threadIdx.x, ty = threadIdx.y;
#pragma unroll
    for (int i = 0; i < 32; i += 8)
        t[ty + i][tx] = W[(size_t)(bk * 32 + ty + i) * D_ + bn * 32 + tx];
    __syncthreads();
#pragma unroll
    for (int i = 0; i < 32; i += 8) {
        int n = bn * 32 + ty + i;
        int k = bk * 32 + tx;
        Wt[(size_t)n * K1_ + k] = __float2half_rn(t[tx][ty + i]);
    }
}

// ---------------------------------------------------------------------------
// HMMA GEMM: 128x256 tile, BK=64, 2-stage cp.async, 256 thr, warps 2m x 4n,
// warp tile 64x64. 96 KB smem -> 2 CTAs/SM.
// mode 0: C[M,1024] fp32. mode 1: QKV (N=3072): n<2048 -> C[m*2048+n] fp32;
// else Vh[m*1024+n-2048] fp16.
// ---------------------------------------------------------------------------
#define STG_A   16384              // 128 rows * 128 B
#define STG_B   32768              // 256 rows * 128 B
#define STG_SZ  (STG_A + STG_B)    // 49152
#define N_STAGE 2                  // 98304 B total

__device__ __forceinline__ uint32_t smem_u32(const void* p) {
    uint32_t a;
    asm("{ .reg .u64 t; cvta.to.shared.u64 t, %1; cvt.u32.u64 %0, t; }"
        : "=r"(a) : "l"(p));
    return a;
}

__device__ __forceinline__ void cp16(uint32_t dst, const void* src) {
    asm volatile("cp.async.cg.shared.global [%0], [%1], 16;\n"
                 :: "r"(dst), "l"(src));
}

__global__ __launch_bounds__(256) void gemm_ms(
    const __half* __restrict__ A,
    const __half* __restrict__ Bt,
    float* __restrict__ C, __half* __restrict__ Vh,
    int mode)
{
    extern __shared__ char smem[];
    const uint32_t sbase = smem_u32(smem);
    const int tid = threadIdx.x;
    const int wid = tid >> 5;
    const int lid = tid & 31;
    const int wm  = wid >> 2;          // 0..1  (64-row block)
    const int wn  = wid & 3;           // 0..3  (64-col block)
    const int nb = blockIdx.x;
    const int mb = blockIdx.y;

    const __half* Ab = A  + (size_t)(mb * 128) * K1_;
    const __half* Bb = Bt + (size_t)(nb * 256) * K1_;

    // load patterns (16B chunks): A 4/thread, B 8/thread
    uint32_t soffA[4]; int ar[4], ac[4];
#pragma unroll
    for (int i = 0; i < 4; i++) {
        int idx = i * 256 + tid;           // 0..1023
        int r = idx >> 3, c = idx & 7;
        ar[i] = r; ac[i] = c;
        soffA[i] = (uint32_t)(r * 128 + (c ^ (r & 7)) * 16);
    }
    uint32_t soffB[8]; int br[8], bc[8];
#pragma unroll
    for (int i = 0; i < 8; i++) {
        int idx = i * 256 + tid;           // 0..2047
        int r = idx >> 3, c = idx & 7;
        br[i] = r; bc[i] = c;
        soffB[i] = (uint32_t)(r * 128 + (c ^ (r & 7)) * 16);
    }

    float acc[4][8][4];
#pragma unroll
    for (int mi = 0; mi < 4; mi++)
#pragma unroll
        for (int ni = 0; ni < 8; ni++)
#pragma unroll
            for (int e = 0; e < 4; e++) acc[mi][ni][e] = 0.0f;

    const int a_row = wm * 64 + (lid & 15);
    const int a_kh  = lid >> 4;
    const int b_row = wn * 64 + ((lid >> 4) * 8) + (lid & 7);
    const int b_kh  = (lid >> 3) & 1;

    // prologue: stage 0
#pragma unroll
    for (int i = 0; i < 4; i++)
        cp16(sbase + soffA[i], Ab + (size_t)ar[i] * K1_ + ac[i] * 8);
#pragma unroll
    for (int i = 0; i < 8; i++)
        cp16(sbase + STG_A + soffB[i], Bb + (size_t)br[i] * K1_ + bc[i] * 8);
    asm volatile("cp.async.commit_group;\n");

    for (int it = 0; it < NT_; ++it) {
        if (it + 1 < NT_) {
            const uint32_t st = sbase + ((it + 1) & 1) * STG_SZ;
            const int k0 = (it + 1) * 64;
#pragma unroll
            for (int i = 0; i < 4; i++)
                cp16(st + soffA[i], Ab + (size_t)ar[i] * K1_ + k0 + ac[i] * 8);
#pragma unroll
            for (int i = 0; i < 8; i++)
                cp16(st + STG_A + soffB[i], Bb + (size_t)br[i] * K1_ + k0 + bc[i] * 8);
            asm volatile("cp.async.commit_group;\n");
            asm volatile("cp.async.wait_group 1;\n");
        } else {
            asm volatile("cp.async.wait_group 0;\n");
        }
        __syncthreads();

        const uint32_t sa = sbase + (it & 1) * STG_SZ;
        const uint32_t sb = sa + STG_A;

#pragma unroll
        for (int k16 = 0; k16 < 4; k16++) {
            uint32_t af[4][4];
#pragma unroll
            for (int mi = 0; mi < 4; mi++) {
                int row = a_row + mi * 16;
                int ch  = (k16 * 2 + a_kh) ^ (row & 7);
                asm volatile(
                    "ldmatrix.sync.aligned.m8n8.x4.shared.b16 {%0,%1,%2,%3}, [%4];"
                    : "=r"(af[mi][0]), "=r"(af[mi][1]), "=r"(af[mi][2]), "=r"(af[mi][3])
                    : "r"(sa + row * 128 + ch * 16));
            }
            uint32_t bf[8][2];
#pragma unroll
            for (int nj = 0; nj < 4; nj++) {
                int row = b_row + nj * 16;
                int ch  = (k16 * 2 + b_kh) ^ (row & 7);
                uint32_t r0, r1, r2, r3;
                asm volatile(
                    "ldmatrix.sync.aligned.m8n8.x4.shared.b16 {%0,%1,%2,%3}, [%4];"
                    : "=r"(r0), "=r"(r1), "=r"(r2), "=r"(r3)
                    : "r"(sb + row * 128 + ch * 16));
                bf[nj * 2 + 0][0] = r0; bf[nj * 2 + 0][1] = r1;
                bf[nj * 2 + 1][0] = r2; bf[nj * 2 + 1][1] = r3;
            }
#pragma unroll
            for (int mi = 0; mi < 4; mi++)
#pragma unroll
                for (int ni = 0; ni < 8; ni++) {
                    asm volatile(
                        "mma.sync.aligned.m16n8k16.row.col.f32.f16.f16.f32 "
                        "{%0,%1,%2,%3}, {%4,%5,%6,%7}, {%8,%9}, {%0,%1,%2,%3};"
                        : "+f"(acc[mi][ni][0]), "+f"(acc[mi][ni][1]),
                          "+f"(acc[mi][ni][2]), "+f"(acc[mi][ni][3])
                        : "r"(af[mi][0]), "r"(af[mi][1]), "r"(af[mi][2]), "r"(af[mi][3]),
                          "r"(bf[ni][0]), "r"(bf[ni][1]));
                }
        }
        __syncthreads();
    }

    // Epilogue (row-major)
    const int nbase = nb * 256;
    const int tq = lid >> 2;
    const int tr = lid & 3;
#pragma unroll
    for (int mi = 0; mi < 4; mi++) {
#pragma unroll
        for (int half_ = 0; half_ < 2; half_++) {
            int m = mb * 128 + wm * 64 + mi * 16 + tq + half_ * 8;
#pragma unroll
            for (int ni = 0; ni < 8; ni++) {
                int n = nbase + wn * 64 + ni * 8 + tr * 2;
                float vx = acc[mi][ni][half_ * 2 + 0];
                float vy = acc[mi][ni][half_ * 2 + 1];
                if (mode == 0) {
                    *(float2*)(C + (size_t)m * 1024 + n) = make_float2(vx, vy);
                } else if (n < 2048) {
                    *(float2*)(C + (size_t)m * 2048 + n) = make_float2(vx, vy);
                } else {
                    union { uint32_t u; __half2 p; } w;
                    w.p = __floats2half2_rn(vx, vy);
                    *(uint32_t*)(Vh + (size_t)m * 1024 + (n - 2048)) = w.u;
                }
            }
        }
    }
}

// ---------------------------------------------------------------------------
// Tensor-core attention v2 (validated R13/R14): one block per (b,h), 4 warps.
// ---------------------------------------------------------------------------
#define QK_ROWB 272
#define V_ROWB  144
#define AT_QS   0
#define AT_KS   (64 * QK_ROWB)
#define AT_VS   (2 * 64 * QK_ROWB)
#define AT_SMEM (AT_VS + 64 * V_ROWB)  // 44032

__global__ __launch_bounds__(128, 4) void attn_tc(
    const float* __restrict__ gqk, const __half* __restrict__ gvh,
    const float* __restrict__ gbias, __half* __restrict__ gout)
{
    extern __shared__ char smc[];
    const uint32_t sb = smem_u32(smc);
    const int tid = threadIdx.x;
    const int wid = tid >> 5;
    const int lid = tid & 31;
    const int bh  = blockIdx.x;
    const int b   = bh >> 4;
    const int h   = bh & 15;

#pragma unroll
    for (int it = 0; it < 8; it++) {
        int e   = it * 128 + tid;
        int row = e >> 4;
        int c4  = e & 15;
        const size_t mrow = (size_t)(b * 64 + row);
        float4 q4 = *(const float4*)(gqk + mrow * 2048 + h * 64 + c4 * 4);
        float4 k4 = *(const float4*)(gqk + mrow * 2048 + 1024 + h * 64 + c4 * 4);
        uint2  v2 = *(const uint2*) (gvh + mrow * 1024 + h * 64 + c4 * 4);
        union { uint4 u; __half2 p[4]; } uq, uk;
        uq.p[0] = split1(q4.x); uq.p[1] = split1(q4.y);
        uq.p[2] = split1(q4.z); uq.p[3] = split1(q4.w);
        uk.p[0] = split1(k4.x); uk.p[1] = split1(k4.y);
        uk.p[2] = split1(k4.z); uk.p[3] = split1(k4.w);
        *(uint4*)(smc + AT_QS + row * QK_ROWB + c4 * 16) = uq.u;
        *(uint4*)(smc + AT_KS + row * QK_ROWB + c4 * 16) = uk.u;
        *(uint2*)(smc + AT_VS + row * V_ROWB + c4 * 8) = v2;
    }
    __syncthreads();

    float SA[8][4];
#pragma unroll
    for (int j = 0; j < 8; j++)
#pragma unroll
        for (int e = 0; e < 4; e++) SA[j][e] = 0.0f;

    const uint32_t a_addr0 = sb + AT_QS + (wid * 16 + (lid & 15)) * QK_ROWB + (lid >> 4) * 16;
    const uint32_t b_rowsel = ((lid >> 4) * 8) + (lid & 7);
    const uint32_t b_khalf  = ((lid >> 3) & 1) * 16;

#pragma unroll
    for (int t = 0; t < 8; t++) {
        uint32_t a0, a1, a2, a3;
        asm volatile(
            "ldmatrix.sync.aligned.m8n8.x4.shared.b16 {%0,%1,%2,%3}, [%4];"
            : "=r"(a0), "=r"(a1), "=r"(a2), "=r"(a3)
            : "r"(a_addr0 + t * 32));
#pragma unroll
        for (int np = 0; np < 4; np++) {
            uint32_t b0, b1, b2, b3;
            uint32_t bd = sb + AT_KS + (np * 16 + b_rowsel) * QK_ROWB + t * 32 + b_khalf;
            asm volatile(
                "ldmatrix.sync.aligned.m8n8.x4.shared.b16 {%0,%1,%2,%3}, [%4];"
                : "=r"(b0), "=r"(b1), "=r"(b2), "=r"(b3)
                : "r"(bd));
            asm volatile(
                "mma.sync.aligned.m16n8k16.row.col.f32.f16.f16.f32 "
                "{%0,%1,%2,%3}, {%4,%5,%6,%7}, {%8,%9}, {%0,%1,%2,%3};"
                : "+f"(SA[2 * np][0]), "+f"(SA[2 * np][1]),
                  "+f"(SA[2 * np][2]), "+f"(SA[2 * np][3])
                : "r"(a0), "r"(a1), "r"(a2), "r"(a3), "r"(b0), "r"(b1));
            asm volatile(
                "mma.sync.aligned.m16n8k16.row.col.f32.f16.f16.f32 "
                "{%0,%1,%2,%3}, {%4,%5,%6,%7}, {%8,%9}, {%0,%1,%2,%3};"
                : "+f"(SA[2 * np + 1][0]), "+f"(SA[2 * np + 1][1]),
                  "+f"(SA[2 * np + 1][2]), "+f"(SA[2 * np + 1][3])
                : "r"(a0), "r"(a1), "r"(a2), "r"(a3), "r"(b2), "r"(b3));
        }
    }

    const int r = lid >> 2;
    const int c = lid & 3;
    const int qr = wid * 16 + r;
    const float* bp0 = gbias + (size_t)h * 4096 + qr * 64;
    const float* bp8 = bp0 + 8 * 64;

    float mx0 = -1e30f, mx8 = -1e30f;
#pragma unroll
    for (int j = 0; j < 8; j++) {
        float2 bb0 = *(const float2*)(bp0 + 8 * j + 2 * c);
        float2 bb8 = *(const float2*)(bp8 + 8 * j + 2 * c);
        SA[j][0] = SA[j][0] * 0.125f + bb0.x;
        SA[j][1] = SA[j][1] * 0.125f + bb0.y;
        SA[j][2] = SA[j][2] * 0.125f + bb8.x;
        SA[j][3] = SA[j][3] * 0.125f + bb8.y;
        mx0 = fmaxf(mx0, fmaxf(SA[j][0], SA[j][1]));
        mx8 = fmaxf(mx8, fmaxf(SA[j][2], SA[j][3]));
    }
    mx0 = fmaxf(mx0, __shfl_xor_sync(0xffffffffu, mx0, 1));
    mx0 = fmaxf(mx0, __shfl_xor_sync(0xffffffffu, mx0, 2));
    mx8 = fmaxf(mx8, __shfl_xor_sync(0xffffffffu, mx8, 1));
    mx8 = fmaxf(mx8, __shfl_xor_sync(0xffffffffu, mx8, 2));

    float s0 = 0.0f, s8 = 0.0f;
#pragma unroll
    for (int j = 0; j < 8; j++) {
        SA[j][0] = __expf(SA[j][0] - mx0); s0 += SA[j][0];
        SA[j][1] = __expf(SA[j][1] - mx0); s0 += SA[j][1];
        SA[j][2] = __expf(SA[j][2] - mx8); s8 += SA[j][2];
        SA[j][3] = __expf(SA[j][3] - mx8); s8 += SA[j][3];
    }
    s0 += __shfl_xor_sync(0xffffffffu, s0, 1);
    s0 += __shfl_xor_sync(0xffffffffu, s0, 2);
    s8 += __shfl_xor_sync(0xffffffffu, s8, 1);
    s8 += __shfl_xor_sync(0xffffffffu, s8, 2);
    const float inv0 = 1.0f / s0, inv8 = 1.0f / s8;
#pragma unroll
    for (int j = 0; j < 8; j++) {
        SA[j][0] *= inv0; SA[j][1] *= inv0;
        SA[j][2] *= inv8; SA[j][3] *= inv8;
    }

    float OA[8][4];
#pragma unroll
    for (int j = 0; j < 8; j++)
#pragma unroll
        for (int e = 0; e < 4; e++) OA[j][e] = 0.0f;

    const uint32_t v_row = (lid & 7) + 8 * ((lid >> 3) & 1);
    const uint32_t v_col = (lid >> 4) * 16;

#pragma unroll
    for (int kt = 0; kt < 4; kt++) {
        uint32_t bf[8][2];
#pragma unroll
        for (int dp = 0; dp < 4; dp++) {
            uint32_t bd = sb + AT_VS + (16 * kt + v_row) * V_ROWB + dp * 32 + v_col;
            uint32_t r0, r1, r2, r3;
            asm volatile(
                "ldmatrix.sync.aligned.m8n8.x4.trans.shared.b16 {%0,%1,%2,%3}, [%4];"
                : "=r"(r0), "=r"(r1), "=r"(r2), "=r"(r3)
                : "r"(bd));
            bf[dp * 2 + 0][0] = r0; bf[dp * 2 + 0][1] = r1;
            bf[dp * 2 + 1][0] = r2; bf[dp * 2 + 1][1] = r3;
        }
        float p00 = SA[2 * kt][0],     p01 = SA[2 * kt][1];
        float p02 = SA[2 * kt][2],     p03 = SA[2 * kt][3];
        float p10 = SA[2 * kt + 1][0], p11 = SA[2 * kt + 1][1];
        float p12 = SA[2 * kt + 1][2], p13 = SA[2 * kt + 1][3];
        __half h00 = __float2half_rn(p00), h01 = __float2half_rn(p01);
        __half h02 = __float2half_rn(p02), h03 = __float2half_rn(p03);
        __half h10 = __float2half_rn(p10), h11 = __float2half_rn(p11);
        __half h12 = __float2half_rn(p12), h13 = __float2half_rn(p13);
        union { uint32_t u; __half2 p; } ah0, ah1, ah2, ah3, al0, al1, al2, al3;
        ah0.p = __halves2half2(h00, h01);
        ah1.p = __halves2half2(h02, h03);
        ah2.p = __halves2half2(h10, h11);
        ah3.p = __halves2half2(h12, h13);
        al0.p = __floats2half2_rn(p00 - __half2float(h00), p01 - __half2float(h01));
        al1.p = __floats2half2_rn(p02 - __half2float(h02), p03 - __half2float(h03));
        al2.p = __floats2half2_rn(p10 - __half2float(h10), p11 - __half2float(h11));
        al3.p = __floats2half2_rn(p12 - __half2float(h12), p13 - __half2float(h13));

#pragma unroll
        for (int ni = 0; ni < 8; ni++) {
            asm volatile(
                "mma.sync.aligned.m16n8k16.row.col.f32.f16.f16.f32 "
                "{%0,%1,%2,%3}, {%4,%5,%6,%7}, {%8,%9}, {%0,%1,%2,%3};"
                : "+f"(OA[ni][0]), "+f"(OA[ni][1]),
                  "+f"(OA[ni][2]), "+f"(OA[ni][3])
                : "r"(ah0.u), "r"(ah1.u), "r"(ah2.u), "r"(ah3.u),
                  "r"(bf[ni][0]), "r"(bf[ni][1]));
            asm volatile(
                "mma.sync.aligned.m16n8k16.row.col.f32.f16.f16.f32 "
                "{%0,%1,%2,%3}, {%4,%5,%6,%7}, {%8,%9}, {%0,%1,%2,%3};"
                : "+f"(OA[ni][0]), "+f"(OA[ni][1]),
                  "+f"(OA[ni][2]), "+f"(OA[ni][3])
                : "r"(al0.u), "r"(al1.u), "r"(al2.u), "r"(al3.u),
                  "r"(bf[ni][0]), "r"(bf[ni][1]));
        }
    }

    const int m = b * 64 + qr;
#pragma unroll
    for (int j = 0; j < 8; j++) {
        int d = 8 * j + 2 * c;
        size_t col = (size_t)(h * 64 + d);
        union { uint32_t u; __half2 p; } w;
        w.p = __floats2half2_rn(OA[j][0], OA[j][1]);
        *(uint32_t*)(gout + (size_t)m * K1_ + col) = w.u;
        w.p = __floats2half2_rn(OA[j][2], OA[j][3]);
        *(uint32_t*)(gout + (size_t)(m + 8) * K1_ + col) = w.u;
    }
}

// ---------------------------------------------------------------------------
// Launch
// ---------------------------------------------------------------------------
extern "C" void kernel_launch(void* const* d_in, const int* in_sizes, int n_in,
                              void* d_out, int out_size)
{
    const float* x    = (const float*)d_in[0];
    const float* bias = (const float*)d_in[1];
    const float* Wq   = (const float*)d_in[2];
    const float* Wk   = (const float*)d_in[3];
    const float* Wv   = (const float*)d_in[4];
    const float* Wo   = (const float*)d_in[5];
    float* out = (float*)d_out;

    void *pxs, *pats, *pwqkv, *pwo, *pqk, *pvh;
    cudaGetSymbolAddress(&pxs,   g_xs);
    cudaGetSymbolAddress(&pats,  g_ats);
    cudaGetSymbolAddress(&pwqkv, g_wqkv);
    cudaGetSymbolAddress(&pwo,   g_wo);
    cudaGetSymbolAddress(&pqk,   g_qk);
    cudaGetSymbolAddress(&pvh,   g_vh);

    // 1. convert inputs to fp16
    conv_rows<<<(M_ * D_ / 8 + 255) / 256, 256>>>(x, (__half*)pxs, M_ * D_ / 8);
    dim3 wt_threads(32, 8), wt_grid(32, 32, 4);
    conv_w_t<<<wt_grid, wt_threads>>>(Wq, Wk, Wv, Wo, (__half*)pwqkv, (__half*)pwo);

    // 2. fused QKV projection (N=3072, 256-wide tiles)
    const int smem_gemm = N_STAGE * STG_SZ;   // 98304
    cudaFuncSetAttribute(gemm_ms, cudaFuncAttributeMaxDynamicSharedMemorySize, smem_gemm);
    dim3 gqkv(3 * D_ / 256, M_ / 128);   // (12, 256)
    gemm_ms<<<gqkv, 256, smem_gemm>>>((const __half*)pxs, (const __half*)pwqkv,
                                      (float*)pqk, (__half*)pvh, 1);

    // 3. tensor-core attention (emits fp16)
    cudaFuncSetAttribute(attn_tc, cudaFuncAttributeMaxDynamicSharedMemorySize, AT_SMEM);
    attn_tc<<<B_ * H_, 128, AT_SMEM>>>((const float*)pqk, (const __half*)pvh,
                                       bias, (__half*)pats);

    // 4. output projection
    dim3 go(D_ / 256, M_ / 128);   // (4, 256)
    gemm_ms<<<go, 256, smem_gemm>>>((const __half*)pats, (const __half*)pwo,
                                    out, (__half*)pvh, 0);
}

// round 17
// speedup vs baseline: 1.1884x; 1.1884x over previous
#include <cuda_runtime.h>
#include <cuda_fp16.h>
#include <cstdint>
#include <math.h>

// Problem constants
#define B_   512
#define L_   64
#define H_   16
#define DH_  64
#define D_   1024
#define M_   (B_ * L_)        // 32768
#define K1_  1024             // fp16 K
#define NT_  (K1_ / 64)       // 16 K-tiles of 64 halfs

// ---------------------------------------------------------------------------
// Scratch (__device__ globals — no allocations allowed)
// ---------------------------------------------------------------------------
__device__ __half    g_xs  [(size_t)M_ * K1_];      // x fp16      [M, 1024]
__device__ __half    g_ats [(size_t)M_ * K1_];      // attn fp16   [M, 1024]
__device__ __half    g_wqkv[(size_t)3 * D_ * K1_];  // [Wq;Wk;Wv]^T fp16
__device__ __half    g_wo  [(size_t)D_ * K1_];      // Wo^T fp16
__device__ uint32_t  g_qk  [(size_t)M_ * 2048];     // [M, 2048]: Q|K packed (hi,lo) half2
__device__ __half    g_vh  [(size_t)M_ * 1024];     // [M, 1024]: V fp16

__device__ __forceinline__ __half2 split1(float v) {
    __half hi = __float2half_rn(v);
    __half lo = __float2half_rn(v - __half2float(hi));
    __half2 p; p.x = hi; p.y = lo; return p;
}
__device__ __forceinline__ uint32_t split1u(float v) {
    union { uint32_t u; __half2 p; } w;
    w.p = split1(v);
    return w.u;
}

// ---------------------------------------------------------------------------
// fp32 -> fp16 conversions
// ---------------------------------------------------------------------------
__global__ __launch_bounds__(256) void conv_rows(
    const float* __restrict__ in, __half* __restrict__ out, int n8)
{
    int i = blockIdx.x * blockDim.x + threadIdx.x;
    if (i >= n8) return;
    float4 a = ((const float4*)in)[2 * i];
    float4 b = ((const float4*)in)[2 * i + 1];
    union { uint4 u; __half2 p[4]; } pk;
    pk.p[0] = __floats2half2_rn(a.x, a.y);
    pk.p[1] = __floats2half2_rn(a.z, a.w);
    pk.p[2] = __floats2half2_rn(b.x, b.y);
    pk.p[3] = __floats2half2_rn(b.z, b.w);
    ((uint4*)out)[i] = pk.u;
}

__global__ __launch_bounds__(256) void conv_w_t(
    const float* __restrict__ W0, const float* __restrict__ W1,
    const float* __restrict__ W2, const float* __restrict__ W3,
    __half* __restrict__ O0, __half* __restrict__ O3)
{
    __shared__ float t[32][33];
    const int which = blockIdx.z;
    const float* W = (which == 0) ? W0 : (which == 1) ? W1 : (which == 2) ? W2 : W3;
    __half* Wt = (which == 3) ? O3 : (O0 + (size_t)which * D_ * K1_);

    const int bn = blockIdx.x, bk = blockIdx.y;
    const int tx = threadIdx.x, ty = threadIdx.y;
#pragma unroll
    for (int i = 0; i < 32; i += 8)
        t[ty + i][tx] = W[(size_t)(bk * 32 + ty + i) * D_ + bn * 32 + tx];
    __syncthreads();
#pragma unroll
    for (int i = 0; i < 32; i += 8) {
        int n = bn * 32 + ty + i;
        int k = bk * 32 + tx;
        Wt[(size_t)n * K1_ + k] = __float2half_rn(t[tx][ty + i]);
    }
}

// ---------------------------------------------------------------------------
// HMMA GEMM (validated R14 config): 128x128 tile, BK=64, 3-stage cp.async,
// 8 warps (2m x 4n), warp tile 64x32. 96 KB smem -> 2 CTAs/SM.
// mode 0: C[M,1024] fp32. mode 1: QKV (N=3072): n<2048 -> Qk[m*2048+n]
// packed (hi,lo) half2; else Vh[m*1024+n-2048] fp16.
// ---------------------------------------------------------------------------
#define STAGE_BYTES 32768
#define SMEM_B_OFF  16384
#define N_STAGE     3

__device__ __forceinline__ uint32_t smem_u32(const void* p) {
    uint32_t a;
    asm("{ .reg .u64 t; cvta.to.shared.u64 t, %1; cvt.u32.u64 %0, t; }"
        : "=r"(a) : "l"(p));
    return a;
}

__device__ __forceinline__ void cp16(uint32_t dst, const void* src) {
    asm volatile("cp.async.cg.shared.global [%0], [%1], 16;\n"
                 :: "r"(dst), "l"(src));
}

__global__ __launch_bounds__(256) void gemm_ms(
    const __half* __restrict__ A,
    const __half* __restrict__ Bt,
    float* __restrict__ C, uint32_t* __restrict__ Qk, __half* __restrict__ Vh,
    int mode)
{
    extern __shared__ char smem[];
    const uint32_t sbase = smem_u32(smem);
    const int tid = threadIdx.x;
    const int wid = tid >> 5;
    const int lid = tid & 31;
    const int wm  = wid >> 2;
    const int wn  = wid & 3;
    const int nb = blockIdx.x;
    const int mb = blockIdx.y;

    const __half* Ab = A  + (size_t)(mb * 128) * K1_;
    const __half* Bb = Bt + (size_t)(nb * 128) * K1_;

    uint32_t soff[4]; int lr[4], lc[4];
#pragma unroll
    for (int i = 0; i < 4; i++) {
        int idx = i * 256 + tid;
        int r = idx >> 3, c = idx & 7;
        lr[i] = r; lc[i] = c;
        soff[i] = (uint32_t)(r * 128 + (c ^ (r & 7)) * 16);
    }

    float acc[4][4][4];
#pragma unroll
    for (int mi = 0; mi < 4; mi++)
#pragma unroll
        for (int ni = 0; ni < 4; ni++)
#pragma unroll
            for (int e = 0; e < 4; e++) acc[mi][ni][e] = 0.0f;

    const int a_row = wm * 64 + (lid & 15);
    const int a_kh  = lid >> 4;
    const int b_row = wn * 32 + ((lid >> 4) * 8) + (lid & 7);
    const int b_kh  = (lid >> 3) & 1;

#pragma unroll
    for (int s = 0; s < 2; s++) {
        const uint32_t st = sbase + s * STAGE_BYTES;
        const int k0 = s * 64;
#pragma unroll
        for (int i = 0; i < 4; i++) {
            cp16(st + soff[i],              Ab + (size_t)lr[i] * K1_ + k0 + lc[i] * 8);
            cp16(st + SMEM_B_OFF + soff[i], Bb + (size_t)lr[i] * K1_ + k0 + lc[i] * 8);
        }
        asm volatile("cp.async.commit_group;\n");
    }

    int cm_stage = 0;
    int ld_stage = 2;

    for (int it = 0; it < NT_; ++it) {
        if (it + 1 < NT_) asm volatile("cp.async.wait_group 1;\n");
        else              asm volatile("cp.async.wait_group 0;\n");
        __syncthreads();

        if (it + 2 < NT_) {
            const uint32_t st = sbase + ld_stage * STAGE_BYTES;
            const int k0 = (it + 2) * 64;
#pragma unroll
            for (int i = 0; i < 4; i++) {
                cp16(st + soff[i],              Ab + (size_t)lr[i] * K1_ + k0 + lc[i] * 8);
                cp16(st + SMEM_B_OFF + soff[i], Bb + (size_t)lr[i] * K1_ + k0 + lc[i] * 8);
            }
            asm volatile("cp.async.commit_group;\n");
            if (++ld_stage == N_STAGE) ld_stage = 0;
        }

        const uint32_t sa = sbase + cm_stage * STAGE_BYTES;
        const uint32_t sb = sa + SMEM_B_OFF;
        if (++cm_stage == N_STAGE) cm_stage = 0;

#pragma unroll
        for (int k16 = 0; k16 < 4; k16++) {
            uint32_t af[4][4];
#pragma unroll
            for (int mi = 0; mi < 4; mi++) {
                int row = a_row + mi * 16;
                int ch  = (k16 * 2 + a_kh) ^ (row & 7);
                uint32_t ad = sa + row * 128 + ch * 16;
                asm volatile(
                    "ldmatrix.sync.aligned.m8n8.x4.shared.b16 {%0,%1,%2,%3}, [%4];"
                    : "=r"(af[mi][0]), "=r"(af[mi][1]), "=r"(af[mi][2]), "=r"(af[mi][3])
                    : "r"(ad));
            }
            uint32_t bf[4][2];
#pragma unroll
            for (int nj = 0; nj < 2; nj++) {
                int row = b_row + nj * 16;
                int ch  = (k16 * 2 + b_kh) ^ (row & 7);
                uint32_t bd = sb + row * 128 + ch * 16;
                uint32_t r0, r1, r2, r3;
                asm volatile(
                    "ldmatrix.sync.aligned.m8n8.x4.shared.b16 {%0,%1,%2,%3}, [%4];"
                    : "=r"(r0), "=r"(r1), "=r"(r2), "=r"(r3)
                    : "r"(bd));
                bf[nj * 2 + 0][0] = r0; bf[nj * 2 + 0][1] = r1;
                bf[nj * 2 + 1][0] = r2; bf[nj * 2 + 1][1] = r3;
            }
#pragma unroll
            for (int mi = 0; mi < 4; mi++)
#pragma unroll
                for (int ni = 0; ni < 4; ni++) {
                    asm volatile(
                        "mma.sync.aligned.m16n8k16.row.col.f32.f16.f16.f32 "
                        "{%0,%1,%2,%3}, {%4,%5,%6,%7}, {%8,%9}, {%0,%1,%2,%3};"
                        : "+f"(acc[mi][ni][0]), "+f"(acc[mi][ni][1]),
                          "+f"(acc[mi][ni][2]), "+f"(acc[mi][ni][3])
                        : "r"(af[mi][0]), "r"(af[mi][1]), "r"(af[mi][2]), "r"(af[mi][3]),
                          "r"(bf[ni][0]), "r"(bf[ni][1]));
                }
        }
    }

    // Epilogue (row-major)
    const int nbase = nb * 128;
    const int tq = lid >> 2;
    const int tr = lid & 3;
#pragma unroll
    for (int mi = 0; mi < 4; mi++) {
#pragma unroll
        for (int half_ = 0; half_ < 2; half_++) {
            int m = mb * 128 + wm * 64 + mi * 16 + tq + half_ * 8;
#pragma unroll
            for (int ni = 0; ni < 4; ni++) {
                int n = nbase + wn * 32 + ni * 8 + tr * 2;
                float vx = acc[mi][ni][half_ * 2 + 0];
                float vy = acc[mi][ni][half_ * 2 + 1];
                if (mode == 0) {
                    *(float2*)(C + (size_t)m * 1024 + n) = make_float2(vx, vy);
                } else if (n < 2048) {
                    uint2 pk;
                    pk.x = split1u(vx);
                    pk.y = split1u(vy);
                    *(uint2*)(Qk + (size_t)m * 2048 + n) = pk;
                } else {
                    union { uint32_t u; __half2 p; } w;
                    w.p = __floats2half2_rn(vx, vy);
                    *(uint32_t*)(Vh + (size_t)m * 1024 + (n - 2048)) = w.u;
                }
            }
        }
    }
}

// ---------------------------------------------------------------------------
// Tensor-core attention v3: one block per (b,h), 4 warps x 16 Q-rows.
// Q,K arrive PRE-SPLIT as packed (hi,lo) half2 -> load phase is pure cp.async.
// S via 2-term interleave, K'=128. P.V via two passes (Phi, Plo), shuffle-free.
// ---------------------------------------------------------------------------
#define QK_ROWB 272               // 128 halfs (=64 packed u32) + 16B pad
#define V_ROWB  144
#define AT_QS   0
#define AT_KS   (64 * QK_ROWB)    // 17408
#define AT_VS   (2 * 64 * QK_ROWB)// 34816
#define AT_SMEM (AT_VS + 64 * V_ROWB)  // 44032

__global__ __launch_bounds__(128, 4) void attn_tc(
    const uint32_t* __restrict__ gqk, const __half* __restrict__ gvh,
    const float* __restrict__ gbias, __half* __restrict__ gout)
{
    extern __shared__ char smc[];
    const uint32_t sb = smem_u32(smc);
    const int tid = threadIdx.x;
    const int wid = tid >> 5;
    const int lid = tid & 31;
    const int bh  = blockIdx.x;
    const int b   = bh >> 4;
    const int h   = bh & 15;

    // ---- pure cp.async load phase: Q,K (pre-split) and V ----
    // Q,K: 1024 x 16B chunks each (8/thread); V: 512 x 16B chunks (4/thread)
#pragma unroll
    for (int it = 0; it < 8; it++) {
        int e   = it * 128 + tid;     // 0..1023
        int row = e >> 4;
        int c4  = e & 15;             // 16B chunk = 4 packed u32 = 4 elems
        const size_t mrow = (size_t)(b * 64 + row);
        const uint32_t* qsrc = gqk + mrow * 2048 + h * 64 + c4 * 4;
        const uint32_t* ksrc = gqk + mrow * 2048 + 1024 + h * 64 + c4 * 4;
        cp16(sb + AT_QS + row * QK_ROWB + c4 * 16, qsrc);
        cp16(sb + AT_KS + row * QK_ROWB + c4 * 16, ksrc);
    }
#pragma unroll
    for (int it = 0; it < 4; it++) {
        int e   = it * 128 + tid;     // 0..511
        int row = e >> 3;
        int c8  = e & 7;              // 16B chunk = 8 halfs
        const size_t mrow = (size_t)(b * 64 + row);
        cp16(sb + AT_VS + row * V_ROWB + c8 * 16, gvh + mrow * 1024 + h * 64 + c8 * 8);
    }
    asm volatile("cp.async.commit_group;\n");
    asm volatile("cp.async.wait_group 0;\n");
    __syncthreads();

    // ---- S = Q.K^T ----
    float SA[8][4];
#pragma unroll
    for (int j = 0; j < 8; j++)
#pragma unroll
        for (int e = 0; e < 4; e++) SA[j][e] = 0.0f;

    const uint32_t a_addr0 = sb + AT_QS + (wid * 16 + (lid & 15)) * QK_ROWB + (lid >> 4) * 16;
    const uint32_t b_rowsel = ((lid >> 4) * 8) + (lid & 7);
    const uint32_t b_khalf  = ((lid >> 3) & 1) * 16;

#pragma unroll
    for (int t = 0; t < 8; t++) {
        uint32_t a0, a1, a2, a3;
        asm volatile(
            "ldmatrix.sync.aligned.m8n8.x4.shared.b16 {%0,%1,%2,%3}, [%4];"
            : "=r"(a0), "=r"(a1), "=r"(a2), "=r"(a3)
            : "r"(a_addr0 + t * 32));
#pragma unroll
        for (int np = 0; np < 4; np++) {
            uint32_t b0, b1, b2, b3;
            uint32_t bd = sb + AT_KS + (np * 16 + b_rowsel) * QK_ROWB + t * 32 + b_khalf;
            asm volatile(
                "ldmatrix.sync.aligned.m8n8.x4.shared.b16 {%0,%1,%2,%3}, [%4];"
                : "=r"(b0), "=r"(b1), "=r"(b2), "=r"(b3)
                : "r"(bd));
            asm volatile(
                "mma.sync.aligned.m16n8k16.row.col.f32.f16.f16.f32 "
                "{%0,%1,%2,%3}, {%4,%5,%6,%7}, {%8,%9}, {%0,%1,%2,%3};"
                : "+f"(SA[2 * np][0]), "+f"(SA[2 * np][1]),
                  "+f"(SA[2 * np][2]), "+f"(SA[2 * np][3])
                : "r"(a0), "r"(a1), "r"(a2), "r"(a3), "r"(b0), "r"(b1));
            asm volatile(
                "mma.sync.aligned.m16n8k16.row.col.f32.f16.f16.f32 "
                "{%0,%1,%2,%3}, {%4,%5,%6,%7}, {%8,%9}, {%0,%1,%2,%3};"
                : "+f"(SA[2 * np + 1][0]), "+f"(SA[2 * np + 1][1]),
                  "+f"(SA[2 * np + 1][2]), "+f"(SA[2 * np + 1][3])
                : "r"(a0), "r"(a1), "r"(a2), "r"(a3), "r"(b2), "r"(b3));
        }
    }

    // ---- softmax ----
    const int r = lid >> 2;
    const int c = lid & 3;
    const int qr = wid * 16 + r;
    const float* bp0 = gbias + (size_t)h * 4096 + qr * 64;
    const float* bp8 = bp0 + 8 * 64;

    float mx0 = -1e30f, mx8 = -1e30f;
#pragma unroll
    for (int j = 0; j < 8; j++) {
        float2 bb0 = *(const float2*)(bp0 + 8 * j + 2 * c);
        float2 bb8 = *(const float2*)(bp8 + 8 * j + 2 * c);
        SA[j][0] = SA[j][0] * 0.125f + bb0.x;
        SA[j][1] = SA[j][1] * 0.125f + bb0.y;
        SA[j][2] = SA[j][2] * 0.125f + bb8.x;
        SA[j][3] = SA[j][3] * 0.125f + bb8.y;
        mx0 = fmaxf(mx0, fmaxf(SA[j][0], SA[j][1]));
        mx8 = fmaxf(mx8, fmaxf(SA[j][2], SA[j][3]));
    }
    mx0 = fmaxf(mx0, __shfl_xor_sync(0xffffffffu, mx0, 1));
    mx0 = fmaxf(mx0, __shfl_xor_sync(0xffffffffu, mx0, 2));
    mx8 = fmaxf(mx8, __shfl_xor_sync(0xffffffffu, mx8, 1));
    mx8 = fmaxf(mx8, __shfl_xor_sync(0xffffffffu, mx8, 2));

    float s0 = 0.0f, s8 = 0.0f;
#pragma unroll
    for (int j = 0; j < 8; j++) {
        SA[j][0] = __expf(SA[j][0] - mx0); s0 += SA[j][0];
        SA[j][1] = __expf(SA[j][1] - mx0); s0 += SA[j][1];
        SA[j][2] = __expf(SA[j][2] - mx8); s8 += SA[j][2];
        SA[j][3] = __expf(SA[j][3] - mx8); s8 += SA[j][3];
    }
    s0 += __shfl_xor_sync(0xffffffffu, s0, 1);
    s0 += __shfl_xor_sync(0xffffffffu, s0, 2);
    s8 += __shfl_xor_sync(0xffffffffu, s8, 1);
    s8 += __shfl_xor_sync(0xffffffffu, s8, 2);
    const float inv0 = 1.0f / s0, inv8 = 1.0f / s8;
#pragma unroll
    for (int j = 0; j < 8; j++) {
        SA[j][0] *= inv0; SA[j][1] *= inv0;
        SA[j][2] *= inv8; SA[j][3] *= inv8;
    }

    // ---- O = P.V: two passes (Phi, Plo), shuffle-free ----
    float OA[8][4];
#pragma unroll
    for (int j = 0; j < 8; j++)
#pragma unroll
        for (int e = 0; e < 4; e++) OA[j][e] = 0.0f;

    const uint32_t v_row = (lid & 7) + 8 * ((lid >> 3) & 1);
    const uint32_t v_col = (lid >> 4) * 16;

#pragma unroll
    for (int kt = 0; kt < 4; kt++) {
        uint32_t bf[8][2];
#pragma unroll
        for (int dp = 0; dp < 4; dp++) {
            uint32_t bd = sb + AT_VS + (16 * kt + v_row) * V_ROWB + dp * 32 + v_col;
            uint32_t r0, r1, r2, r3;
            asm volatile(
                "ldmatrix.sync.aligned.m8n8.x4.trans.shared.b16 {%0,%1,%2,%3}, [%4];"
                : "=r"(r0), "=r"(r1), "=r"(r2), "=r"(r3)
                : "r"(bd));
            bf[dp * 2 + 0][0] = r0; bf[dp * 2 + 0][1] = r1;
            bf[dp * 2 + 1][0] = r2; bf[dp * 2 + 1][1] = r3;
        }
        float p00 = SA[2 * kt][0],     p01 = SA[2 * kt][1];
        float p02 = SA[2 * kt][2],     p03 = SA[2 * kt][3];
        float p10 = SA[2 * kt + 1][0], p11 = SA[2 * kt + 1][1];
        float p12 = SA[2 * kt + 1][2], p13 = SA[2 * kt + 1][3];
        __half h00 = __float2half_rn(p00), h01 = __float2half_rn(p01);
        __half h02 = __float2half_rn(p02), h03 = __float2half_rn(p03);
        __half h10 = __float2half_rn(p10), h11 = __float2half_rn(p11);
        __half h12 = __float2half_rn(p12), h13 = __float2half_rn(p13);
        union { uint32_t u; __half2 p; } ah0, ah1, ah2, ah3, al0, al1, al2, al3;
        ah0.p = __halves2half2(h00, h01);
        ah1.p = __halves2half2(h02, h03);
        ah2.p = __halves2half2(h10, h11);
        ah3.p = __halves2half2(h12, h13);
        al0.p = __floats2half2_rn(p00 - __half2float(h00), p01 - __half2float(h01));
        al1.p = __floats2half2_rn(p02 - __half2float(h02), p03 - __half2float(h03));
        al2.p = __floats2half2_rn(p10 - __half2float(h10), p11 - __half2float(h11));
        al3.p = __floats2half2_rn(p12 - __half2float(h12), p13 - __half2float(h13));

#pragma unroll
        for (int ni = 0; ni < 8; ni++) {
            asm volatile(
                "mma.sync.aligned.m16n8k16.row.col.f32.f16.f16.f32 "
                "{%0,%1,%2,%3}, {%4,%5,%6,%7}, {%8,%9}, {%0,%1,%2,%3};"
                : "+f"(OA[ni][0]), "+f"(OA[ni][1]),
                  "+f"(OA[ni][2]), "+f"(OA[ni][3])
                : "r"(ah0.u), "r"(ah1.u), "r"(ah2.u), "r"(ah3.u),
                  "r"(bf[ni][0]), "r"(bf[ni][1]));
            asm volatile(
                "mma.sync.aligned.m16n8k16.row.col.f32.f16.f16.f32 "
                "{%0,%1,%2,%3}, {%4,%5,%6,%7}, {%8,%9}, {%0,%1,%2,%3};"
                : "+f"(OA[ni][0]), "+f"(OA[ni][1]),
                  "+f"(OA[ni][2]), "+f"(OA[ni][3])
                : "r"(al0.u), "r"(al1.u), "r"(al2.u), "r"(al3.u),
                  "r"(bf[ni][0]), "r"(bf[ni][1]));
        }
    }

    // ---- fp16 epilogue into [M,1024] ----
    const int m = b * 64 + qr;
#pragma unroll
    for (int j = 0; j < 8; j++) {
        int d = 8 * j + 2 * c;
        size_t col = (size_t)(h * 64 + d);
        union { uint32_t u; __half2 p; } w;
        w.p = __floats2half2_rn(OA[j][0], OA[j][1]);
        *(uint32_t*)(gout + (size_t)m * K1_ + col) = w.u;
        w.p = __floats2half2_rn(OA[j][2], OA[j][3]);
        *(uint32_t*)(gout + (size_t)(m + 8) * K1_ + col) = w.u;
    }
}

// ---------------------------------------------------------------------------
// Launch
// ---------------------------------------------------------------------------
extern "C" void kernel_launch(void* const* d_in, const int* in_sizes, int n_in,
                              void* d_out, int out_size)
{
    const float* x    = (const float*)d_in[0];
    const float* bias = (const float*)d_in[1];
    const float* Wq   = (const float*)d_in[2];
    const float* Wk   = (const float*)d_in[3];
    const float* Wv   = (const float*)d_in[4];
    const float* Wo   = (const float*)d_in[5];
    float* out = (float*)d_out;

    void *pxs, *pats, *pwqkv, *pwo, *pqk, *pvh;
    cudaGetSymbolAddress(&pxs,   g_xs);
    cudaGetSymbolAddress(&pats,  g_ats);
    cudaGetSymbolAddress(&pwqkv, g_wqkv);
    cudaGetSymbolAddress(&pwo,   g_wo);
    cudaGetSymbolAddress(&pqk,   g_qk);
    cudaGetSymbolAddress(&pvh,   g_vh);

    // 1. convert inputs to fp16
    conv_rows<<<(M_ * D_ / 8 + 255) / 256, 256>>>(x, (__half*)pxs, M_ * D_ / 8);
    dim3 wt_threads(32, 8), wt_grid(32, 32, 4);
    conv_w_t<<<wt_grid, wt_threads>>>(Wq, Wk, Wv, Wo, (__half*)pwqkv, (__half*)pwo);

    // 2. fused QKV projection (epilogue emits pre-split Q,K + fp16 V)
    const int smem_gemm = N_STAGE * STAGE_BYTES;   // 96 KB
    cudaFuncSetAttribute(gemm_ms, cudaFuncAttributeMaxDynamicSharedMemorySize, smem_gemm);
    dim3 gqkv(3 * D_ / 128, M_ / 128);   // (24, 256)
    gemm_ms<<<gqkv, 256, smem_gemm>>>((const __half*)pxs, (const __half*)pwqkv,
                                      out, (uint32_t*)pqk, (__half*)pvh, 1);

    // 3. tensor-core attention (pure cp.async loads, emits fp16)
    cudaFuncSetAttribute(attn_tc, cudaFuncAttributeMaxDynamicSharedMemorySize, AT_SMEM);
    attn_tc<<<B_ * H_, 128, AT_SMEM>>>((const uint32_t*)pqk, (const __half*)pvh,
                                       bias, (__half*)pats);

    // 4. output projection
    dim3 go(D_ / 128, M_ / 128);   // (8, 256)
    gemm_ms<<<go, 256, smem_gemm>>>((const __half*)pats, (const __half*)pwo,
                                    out, (uint32_t*)pqk, (__half*)pvh, 0);
}